// round 2
// baseline (speedup 1.0000x reference)
#include <cuda_runtime.h>
#include <math.h>

// ---------------------------------------------------------------------------
// DehazeFormer block: fp32 scalar baseline (round 1 — smem-init fix)
// B=4, C=96, H=W=256, ws=8, nh=6, hd=16
// ---------------------------------------------------------------------------

namespace cfg {
constexpr int B = 4, C = 96, H = 256, W = 256, HW = H * W;
constexpr int NH = 6, HD = 16;
constexpr int NPIX = B * HW;                 // 262144
constexpr int NWIN = B * (H / 8) * (W / 8);  // 4096
}

using namespace cfg;

// ---- scratch (static __device__: allocation-free) --------------------------
__device__ float g_V[B * C * HW];        // conv1x1 V output
__device__ float g_QK[B * 2 * C * HW];   // conv1x1 QK output
__device__ float g_attn[B * C * HW];     // attention output (NCHW)
__device__ float g_c1[B * C * HW];       // relu(conv1(V))
__device__ float g_c2[B * C * HW];       // conv2(...)
__device__ float g_bias[NH * 64 * 64];   // attention bias [h][n][m]

// ---------------------------------------------------------------------------
// Kernel 1: relative-position bias MLP  ->  g_bias[h][n][m]
// ---------------------------------------------------------------------------
__global__ void k_bias(const float* __restrict__ w1, const float* __restrict__ b1,
                       const float* __restrict__ w2, const float* __restrict__ b2) {
    int idx = blockIdx.x * blockDim.x + threadIdx.x;  // 0..4095
    if (idx >= 64 * 64) return;
    int n = idx >> 6, m = idx & 63;
    float dy = (float)((n >> 3) - (m >> 3));
    float dx = (float)((n & 7) - (m & 7));
    float sy = (dy > 0.f) ? 1.f : ((dy < 0.f) ? -1.f : 0.f);
    float sx = (dx > 0.f) ? 1.f : ((dx < 0.f) ? -1.f : 0.f);
    float r0 = sy * log1pf(fabsf(dy));
    float r1 = sx * log1pf(fabsf(dx));

    float acc[NH];
#pragma unroll
    for (int h = 0; h < NH; h++) acc[h] = b2[h];
    for (int k = 0; k < 256; k++) {
        float hk = fmaf(r0, w1[k], fmaf(r1, w1[256 + k], b1[k]));
        hk = fmaxf(hk, 0.f);
#pragma unroll
        for (int h = 0; h < NH; h++) acc[h] = fmaf(hk, w2[k * NH + h], acc[h]);
    }
#pragma unroll
    for (int h = 0; h < NH; h++) g_bias[(h * 64 + n) * 64 + m] = acc[h];
}

// ---------------------------------------------------------------------------
// Kernel 2: fused conv1x1 producing QK (192ch) and V (96ch)
// GEMM: out[oc, pix] = W[oc, ic] * X[ic, pix], tile = 128 px, all 288 oc
// smem: X tile [96][128] + combined W [288][96] + bias  (~161 KB)
// ---------------------------------------------------------------------------
constexpr int QKV_SMEM = (C * 128 + 288 * C + 288) * 4;

__global__ __launch_bounds__(256, 1)
void k_qkv(const float* __restrict__ X, const float* __restrict__ Vw,
           const float* __restrict__ Vb, const float* __restrict__ QKw,
           const float* __restrict__ QKb) {
    extern __shared__ float sm[];
    float* Xs = sm;               // C*128
    float* Ws = sm + C * 128;     // 288*C
    float* bs = Ws + 288 * C;     // 288

    const int tid = threadIdx.x;
    const int pix0 = blockIdx.x * 128;
    const int b = pix0 / HW;
    const int p0 = pix0 % HW;
    const float* Xb = X + b * C * HW + p0;

    for (int i = tid; i < C * 128; i += 256)
        Xs[i] = Xb[(i >> 7) * HW + (i & 127)];
    for (int i = tid; i < 288 * C; i += 256)
        Ws[i] = (i < 192 * C) ? QKw[i] : Vw[i - 192 * C];
    for (int i = tid; i < 288; i += 256)          // FIX: full coverage (was if(tid<288))
        bs[i] = (i < 192) ? QKb[i] : Vb[i - 192];
    __syncthreads();

    const int q = tid & 31;   // pixel quad (4 px)
    const int g = tid >> 5;   // oc group (36 oc each)
    const float4* Xs4 = (const float4*)Xs;

    for (int oc0 = g * 36; oc0 < g * 36 + 36; oc0 += 6) {
        float4 acc[6];
#pragma unroll
        for (int o = 0; o < 6; o++) acc[o] = make_float4(0.f, 0.f, 0.f, 0.f);
        for (int ic = 0; ic < C; ic++) {
            float4 xv = Xs4[ic * 32 + q];
#pragma unroll
            for (int o = 0; o < 6; o++) {
                float w = Ws[(oc0 + o) * C + ic];
                acc[o].x = fmaf(w, xv.x, acc[o].x);
                acc[o].y = fmaf(w, xv.y, acc[o].y);
                acc[o].z = fmaf(w, xv.z, acc[o].z);
                acc[o].w = fmaf(w, xv.w, acc[o].w);
            }
        }
#pragma unroll
        for (int o = 0; o < 6; o++) {
            int oc = oc0 + o;
            float bv = bs[oc];
            float4 r = acc[o];
            r.x += bv; r.y += bv; r.z += bv; r.w += bv;
            float* dst = (oc < 192)
                ? &g_QK[(b * 192 + oc) * HW + p0 + q * 4]
                : &g_V[(b * C + (oc - 192)) * HW + p0 + q * 4];
            *(float4*)dst = r;
        }
    }
}

// ---------------------------------------------------------------------------
// Kernel 3: window attention. One block per window (64 px), 6 heads.
// threads: 384 = head (6) x row n (64). K/V in smem pitch 20, scores pitch 65.
// ---------------------------------------------------------------------------
constexpr int KV_PITCH = 20;
constexpr int ATTN_SMEM = (2 * NH * 64 * KV_PITCH + NH * 64 * 65) * 4;

__global__ __launch_bounds__(384, 1)
void k_attn() {
    extern __shared__ float sm[];
    float* Ks = sm;                           // NH*64*20
    float* Vs = Ks + NH * 64 * KV_PITCH;      // NH*64*20
    float* Ss = Vs + NH * 64 * KV_PITCH;      // NH*64*65

    const int tid = threadIdx.x;
    const int win = blockIdx.x;
    const int b = win >> 10;
    const int wy = (win >> 5) & 31, wx = win & 31;
    const int h = tid / 64, n = tid & 63;
    const int pix = (wy * 8 + (n >> 3)) * W + wx * 8 + (n & 7);

    const float* Qg = g_QK + (b * 192 + h * HD) * HW + pix;
    const float* Kg = g_QK + (b * 192 + 96 + h * HD) * HW + pix;
    const float* Vg = g_V + (b * C + h * HD) * HW + pix;

    float qv[HD];
#pragma unroll
    for (int d = 0; d < HD; d++) {
        qv[d] = Qg[d * HW] * 0.25f;  // scale = hd^-0.5
        Ks[(h * 64 + n) * KV_PITCH + d] = Kg[d * HW];
        Vs[(h * 64 + n) * KV_PITCH + d] = Vg[d * HW];
    }
    __syncthreads();

    const float* gb = g_bias + (h * 64 + n) * 64;
    float* srow = Ss + (h * 64 + n) * 65;
    const float4* Kh = (const float4*)(Ks + h * 64 * KV_PITCH);
    const float4* Vh = (const float4*)(Vs + h * 64 * KV_PITCH);

    float mx = -1e30f;
    for (int m = 0; m < 64; m++) {
        float s = gb[m];
#pragma unroll
        for (int t = 0; t < 4; t++) {
            float4 kv = Kh[m * (KV_PITCH / 4) + t];
            s = fmaf(qv[4 * t + 0], kv.x, s);
            s = fmaf(qv[4 * t + 1], kv.y, s);
            s = fmaf(qv[4 * t + 2], kv.z, s);
            s = fmaf(qv[4 * t + 3], kv.w, s);
        }
        srow[m] = s;
        mx = fmaxf(mx, s);
    }
    float sum = 0.f;
    for (int m = 0; m < 64; m++) {
        float p = __expf(srow[m] - mx);
        srow[m] = p;
        sum += p;
    }
    float inv = 1.f / sum;

    float o[HD];
#pragma unroll
    for (int d = 0; d < HD; d++) o[d] = 0.f;
    for (int m = 0; m < 64; m++) {
        float p = srow[m];
#pragma unroll
        for (int t = 0; t < 4; t++) {
            float4 vv = Vh[m * (KV_PITCH / 4) + t];
            o[4 * t + 0] = fmaf(p, vv.x, o[4 * t + 0]);
            o[4 * t + 1] = fmaf(p, vv.y, o[4 * t + 1]);
            o[4 * t + 2] = fmaf(p, vv.z, o[4 * t + 2]);
            o[4 * t + 3] = fmaf(p, vv.w, o[4 * t + 3]);
        }
    }
    float* Og = g_attn + (b * C + h * HD) * HW + pix;
#pragma unroll
    for (int d = 0; d < HD; d++) Og[d * HW] = o[d] * inv;
}

// ---------------------------------------------------------------------------
// Kernel 4/5: conv3x3 reflect-pad (PASS=0: g_V->g_c1 +relu, PASS=1: g_c1->g_c2)
// block: 128 px (4x32 tile) x 32 oc. smem: input halo [96][6][34] + W [96*9][34]
// each thread: 8 px x 2 oc register tile
// ---------------------------------------------------------------------------
constexpr int CONV_XS = 96 * 6 * 34;        // 19584
constexpr int CONV_WS = 96 * 9 * 34;        // 29376 (pitch 34 over 32 oc)
constexpr int CONV_SMEM = (CONV_XS + CONV_WS) * 4;

template <int PASS>
__global__ __launch_bounds__(256, 1)
void k_conv3(const float* __restrict__ wg, const float* __restrict__ bg) {
    const float* in = (PASS == 0) ? g_V : g_c1;
    float* out = (PASS == 0) ? g_c1 : g_c2;
    constexpr bool RELU = (PASS == 0);

    extern __shared__ float sm[];
    float* Xs = sm;             // [ic][row(6)][col(34)]
    float* Ws = sm + CONV_XS;   // [(ic*9+tap)][34] (32 oc used)

    const int tid = threadIdx.x;
    const int xb = blockIdx.x * 32;
    const int yb = blockIdx.y * 4;
    const int bz = blockIdx.z;
    const int b = bz / 3;
    const int ocBase = (bz % 3) * 32;
    const float* inb = in + b * C * HW;

    for (int i = tid; i < CONV_XS; i += 256) {
        int ic = i / 204;
        int r = i % 204;
        int row = r / 34, col = r % 34;
        int gy = yb + row - 1;
        gy = (gy < 0) ? -gy : ((gy > 255) ? 510 - gy : gy);
        int gx = xb + col - 1;
        gx = (gx < 0) ? -gx : ((gx > 255) ? 510 - gx : gx);
        Xs[i] = inb[ic * HW + gy * W + gx];
    }
    for (int i = tid; i < 32 * 96 * 9; i += 256) {
        int o = i / 864;
        int r = i % 864;  // ic*9 + tap
        Ws[r * 34 + o] = wg[(ocBase + o) * 864 + r];
    }
    __syncthreads();

    const int slot = tid & 15, opair = tid >> 4;
    const int orow = slot >> 2, xg = (slot & 3) * 8;
    const int ocL = opair * 2;

    float acc0[8], acc1[8];
#pragma unroll
    for (int j = 0; j < 8; j++) { acc0[j] = 0.f; acc1[j] = 0.f; }

    for (int ic = 0; ic < C; ic++) {
        const float* xic = Xs + ic * 204;
        const float* wic = Ws + ic * 9 * 34 + ocL;
#pragma unroll
        for (int dy = 0; dy < 3; dy++) {
            const float* xr = xic + (orow + dy) * 34 + xg;
            float v[10];
#pragma unroll
            for (int k = 0; k < 10; k++) v[k] = xr[k];
#pragma unroll
            for (int dx = 0; dx < 3; dx++) {
                float2 w = *(const float2*)(wic + (dy * 3 + dx) * 34);
#pragma unroll
                for (int j = 0; j < 8; j++) {
                    acc0[j] = fmaf(w.x, v[j + dx], acc0[j]);
                    acc1[j] = fmaf(w.y, v[j + dx], acc1[j]);
                }
            }
        }
    }

    const int oc = ocBase + ocL;
    const float b0 = bg[oc], b1 = bg[oc + 1];
    float* o0 = out + (b * C + oc) * HW + (yb + orow) * W + xb + xg;
    float* o1 = o0 + HW;
#pragma unroll
    for (int j = 0; j < 8; j++) {
        float r0 = acc0[j] + b0;
        float r1 = acc1[j] + b1;
        if (RELU) { r0 = fmaxf(r0, 0.f); r1 = fmaxf(r1, 0.f); }
        o0[j] = r0;
        o1[j] = r1;
    }
}

// ---------------------------------------------------------------------------
// Kernel 6: proj conv1x1 on (g_c2 + g_attn) -> d_out
// ---------------------------------------------------------------------------
constexpr int PROJ_SMEM = (C * 128 + C * C + C) * 4;

__global__ __launch_bounds__(256, 1)
void k_proj(const float* __restrict__ Pw, const float* __restrict__ Pb,
            float* __restrict__ out) {
    extern __shared__ float sm[];
    float* Xs = sm;              // 96*128
    float* Ws = Xs + C * 128;    // 96*96
    float* bs = Ws + C * C;      // 96

    const int tid = threadIdx.x;
    const int pix0 = blockIdx.x * 128;
    const int b = pix0 / HW;
    const int p0 = pix0 % HW;
    const int base = b * C * HW + p0;

    for (int i = tid; i < C * 128; i += 256) {
        int idx = base + (i >> 7) * HW + (i & 127);
        Xs[i] = g_c2[idx] + g_attn[idx];
    }
    for (int i = tid; i < C * C; i += 256) Ws[i] = Pw[i];
    if (tid < C) bs[tid] = Pb[tid];   // C=96 < blockDim=256: fully covered
    __syncthreads();

    const int q = tid & 31;
    const int g = tid >> 5;
    const float4* Xs4 = (const float4*)Xs;

    for (int oc0 = g * 12; oc0 < g * 12 + 12; oc0 += 6) {
        float4 acc[6];
#pragma unroll
        for (int o = 0; o < 6; o++) acc[o] = make_float4(0.f, 0.f, 0.f, 0.f);
        for (int ic = 0; ic < C; ic++) {
            float4 xv = Xs4[ic * 32 + q];
#pragma unroll
            for (int o = 0; o < 6; o++) {
                float w = Ws[(oc0 + o) * C + ic];
                acc[o].x = fmaf(w, xv.x, acc[o].x);
                acc[o].y = fmaf(w, xv.y, acc[o].y);
                acc[o].z = fmaf(w, xv.z, acc[o].z);
                acc[o].w = fmaf(w, xv.w, acc[o].w);
            }
        }
#pragma unroll
        for (int o = 0; o < 6; o++) {
            int oc = oc0 + o;
            float bv = bs[oc];
            float4 r = acc[o];
            r.x += bv; r.y += bv; r.z += bv; r.w += bv;
            *(float4*)&out[(b * C + oc) * HW + p0 + q * 4] = r;
        }
    }
}

// ---------------------------------------------------------------------------
// launch
// ---------------------------------------------------------------------------
extern "C" void kernel_launch(void* const* d_in, const int* in_sizes, int n_in,
                              void* d_out, int out_size) {
    const float* X   = (const float*)d_in[0];
    const float* Vw  = (const float*)d_in[1];
    const float* Vb  = (const float*)d_in[2];
    const float* QKw = (const float*)d_in[3];
    const float* QKb = (const float*)d_in[4];
    const float* mw1 = (const float*)d_in[5];
    const float* mb1 = (const float*)d_in[6];
    const float* mw2 = (const float*)d_in[7];
    const float* mb2 = (const float*)d_in[8];
    const float* c1w = (const float*)d_in[9];
    const float* c1b = (const float*)d_in[10];
    const float* c2w = (const float*)d_in[11];
    const float* c2b = (const float*)d_in[12];
    const float* pw  = (const float*)d_in[13];
    const float* pb  = (const float*)d_in[14];
    float* out = (float*)d_out;

    cudaFuncSetAttribute(k_qkv, cudaFuncAttributeMaxDynamicSharedMemorySize, QKV_SMEM);
    cudaFuncSetAttribute(k_attn, cudaFuncAttributeMaxDynamicSharedMemorySize, ATTN_SMEM);
    cudaFuncSetAttribute(k_conv3<0>, cudaFuncAttributeMaxDynamicSharedMemorySize, CONV_SMEM);
    cudaFuncSetAttribute(k_conv3<1>, cudaFuncAttributeMaxDynamicSharedMemorySize, CONV_SMEM);
    cudaFuncSetAttribute(k_proj, cudaFuncAttributeMaxDynamicSharedMemorySize, PROJ_SMEM);

    k_bias<<<16, 256>>>(mw1, mb1, mw2, mb2);
    k_qkv<<<NPIX / 128, 256, QKV_SMEM>>>(X, Vw, Vb, QKw, QKb);
    k_attn<<<NWIN, 384, ATTN_SMEM>>>();
    dim3 cgrid(W / 32, H / 4, B * 3);
    k_conv3<0><<<cgrid, 256, CONV_SMEM>>>(c1w, c1b);
    k_conv3<1><<<cgrid, 256, CONV_SMEM>>>(c2w, c2b);
    k_proj<<<NPIX / 128, 256, PROJ_SMEM>>>(pw, pb, out);
}

// round 4
// speedup vs baseline: 1.6788x; 1.6788x over previous
#include <cuda_runtime.h>
#include <math.h>
#include <stdint.h>

// ---------------------------------------------------------------------------
// DehazeFormer block — round 3 (= round 2 resubmit after infra failure):
// conv3x3 -> tf32 mma.sync implicit GEMM
// B=4, C=96, H=W=256, ws=8, nh=6, hd=16
// ---------------------------------------------------------------------------

namespace cfg {
constexpr int B = 4, C = 96, H = 256, W = 256, HW = H * W;
constexpr int NH = 6, HD = 16;
constexpr int NPIX = B * HW;
constexpr int NWIN = B * (H / 8) * (W / 8);
}
using namespace cfg;

// ---- scratch ---------------------------------------------------------------
__device__ float g_V[B * C * HW];
__device__ float g_QK[B * 2 * C * HW];
__device__ float g_attn[B * C * HW];
__device__ float g_c1[B * C * HW];
__device__ float g_c2[B * C * HW];
__device__ float g_bias[NH * 64 * 64];
// permuted tf32 conv weights: [tap][kc(12)][m(96)][8 perm]
__device__ unsigned g_Wt1[9 * 12 * 96 * 8];
__device__ unsigned g_Wt2[9 * 12 * 96 * 8];

__device__ __forceinline__ unsigned f2tf32(float f) {
    unsigned u;
    asm("cvt.rna.tf32.f32 %0, %1;" : "=r"(u) : "f"(f));
    return u;
}
__device__ __forceinline__ int refl(int v) {
    return v < 0 ? -v : (v > 255 ? 510 - v : v);
}

#define MMA_TF32(d0, d1, d2, d3, a0, a1, a2, a3, b0, b1)                        \
    asm volatile(                                                               \
        "mma.sync.aligned.m16n8k8.row.col.f32.tf32.tf32.f32 "                   \
        "{%0,%1,%2,%3}, {%4,%5,%6,%7}, {%8,%9}, {%0,%1,%2,%3};\n"               \
        : "+f"(d0), "+f"(d1), "+f"(d2), "+f"(d3)                                \
        : "r"(a0), "r"(a1), "r"(a2), "r"(a3), "r"(b0), "r"(b1))

// ---------------------------------------------------------------------------
// Kernel 0: weight pre-permute (fp32 -> tf32, mma-fragment-friendly layout)
// dst[((tap*12+kc)*96+m)*8 + pos], pos=2*(k%4)+(k/4), ic=kc*8+k
// ---------------------------------------------------------------------------
__global__ void k_wprep(const float* __restrict__ w1, const float* __restrict__ w2) {
    int e = blockIdx.x * blockDim.x + threadIdx.x;
    if (e >= 9 * 12 * 96 * 8) return;
    int pos = e & 7;
    int m = (e >> 3) % 96;
    int kc = (e >> 3) / 96 % 12;
    int tap = (e >> 3) / (96 * 12);
    int k = ((pos & 1) << 2) + (pos >> 1);
    int ic = kc * 8 + k;
    int src = m * 864 + ic * 9 + tap;
    g_Wt1[e] = f2tf32(w1[src]);
    g_Wt2[e] = f2tf32(w2[src]);
}

// ---------------------------------------------------------------------------
// Kernel 1: relative-position bias MLP
// ---------------------------------------------------------------------------
__global__ void k_bias(const float* __restrict__ w1, const float* __restrict__ b1,
                       const float* __restrict__ w2, const float* __restrict__ b2) {
    int idx = blockIdx.x * blockDim.x + threadIdx.x;
    if (idx >= 64 * 64) return;
    int n = idx >> 6, m = idx & 63;
    float dy = (float)((n >> 3) - (m >> 3));
    float dx = (float)((n & 7) - (m & 7));
    float sy = (dy > 0.f) ? 1.f : ((dy < 0.f) ? -1.f : 0.f);
    float sx = (dx > 0.f) ? 1.f : ((dx < 0.f) ? -1.f : 0.f);
    float r0 = sy * log1pf(fabsf(dy));
    float r1 = sx * log1pf(fabsf(dx));
    float acc[NH];
#pragma unroll
    for (int h = 0; h < NH; h++) acc[h] = b2[h];
    for (int k = 0; k < 256; k++) {
        float hk = fmaf(r0, w1[k], fmaf(r1, w1[256 + k], b1[k]));
        hk = fmaxf(hk, 0.f);
#pragma unroll
        for (int h = 0; h < NH; h++) acc[h] = fmaf(hk, w2[k * NH + h], acc[h]);
    }
#pragma unroll
    for (int h = 0; h < NH; h++) g_bias[(h * 64 + n) * 64 + m] = acc[h];
}

// ---------------------------------------------------------------------------
// Kernel 2: fused conv1x1 producing QK (192ch) and V (96ch)
// ---------------------------------------------------------------------------
constexpr int QKV_SMEM = (C * 128 + 288 * C + 288) * 4;

__global__ __launch_bounds__(256, 1)
void k_qkv(const float* __restrict__ X, const float* __restrict__ Vw,
           const float* __restrict__ Vb, const float* __restrict__ QKw,
           const float* __restrict__ QKb) {
    extern __shared__ float sm[];
    float* Xs = sm;
    float* Ws = sm + C * 128;
    float* bs = Ws + 288 * C;

    const int tid = threadIdx.x;
    const int pix0 = blockIdx.x * 128;
    const int b = pix0 / HW;
    const int p0 = pix0 % HW;
    const float* Xb = X + b * C * HW + p0;

    for (int i = tid; i < C * 128; i += 256)
        Xs[i] = Xb[(i >> 7) * HW + (i & 127)];
    for (int i = tid; i < 288 * C; i += 256)
        Ws[i] = (i < 192 * C) ? QKw[i] : Vw[i - 192 * C];
    for (int i = tid; i < 288; i += 256)
        bs[i] = (i < 192) ? QKb[i] : Vb[i - 192];
    __syncthreads();

    const int q = tid & 31;
    const int g = tid >> 5;
    const float4* Xs4 = (const float4*)Xs;

    for (int oc0 = g * 36; oc0 < g * 36 + 36; oc0 += 6) {
        float4 acc[6];
#pragma unroll
        for (int o = 0; o < 6; o++) acc[o] = make_float4(0.f, 0.f, 0.f, 0.f);
        for (int ic = 0; ic < C; ic++) {
            float4 xv = Xs4[ic * 32 + q];
#pragma unroll
            for (int o = 0; o < 6; o++) {
                float w = Ws[(oc0 + o) * C + ic];
                acc[o].x = fmaf(w, xv.x, acc[o].x);
                acc[o].y = fmaf(w, xv.y, acc[o].y);
                acc[o].z = fmaf(w, xv.z, acc[o].z);
                acc[o].w = fmaf(w, xv.w, acc[o].w);
            }
        }
#pragma unroll
        for (int o = 0; o < 6; o++) {
            int oc = oc0 + o;
            float bv = bs[oc];
            float4 r = acc[o];
            r.x += bv; r.y += bv; r.z += bv; r.w += bv;
            float* dst = (oc < 192)
                ? &g_QK[(b * 192 + oc) * HW + p0 + q * 4]
                : &g_V[(b * C + (oc - 192)) * HW + p0 + q * 4];
            *(float4*)dst = r;
        }
    }
}

// ---------------------------------------------------------------------------
// Kernel 3: window attention
// ---------------------------------------------------------------------------
constexpr int KV_PITCH = 20;
constexpr int ATTN_SMEM = (2 * NH * 64 * KV_PITCH + NH * 64 * 65) * 4;

__global__ __launch_bounds__(384, 1)
void k_attn() {
    extern __shared__ float sm[];
    float* Ks = sm;
    float* Vs = Ks + NH * 64 * KV_PITCH;
    float* Ss = Vs + NH * 64 * KV_PITCH;

    const int tid = threadIdx.x;
    const int win = blockIdx.x;
    const int b = win >> 10;
    const int wy = (win >> 5) & 31, wx = win & 31;
    const int h = tid / 64, n = tid & 63;
    const int pix = (wy * 8 + (n >> 3)) * W + wx * 8 + (n & 7);

    const float* Qg = g_QK + (b * 192 + h * HD) * HW + pix;
    const float* Kg = g_QK + (b * 192 + 96 + h * HD) * HW + pix;
    const float* Vg = g_V + (b * C + h * HD) * HW + pix;

    float qv[HD];
#pragma unroll
    for (int d = 0; d < HD; d++) {
        qv[d] = Qg[d * HW] * 0.25f;
        Ks[(h * 64 + n) * KV_PITCH + d] = Kg[d * HW];
        Vs[(h * 64 + n) * KV_PITCH + d] = Vg[d * HW];
    }
    __syncthreads();

    const float* gb = g_bias + (h * 64 + n) * 64;
    float* srow = Ss + (h * 64 + n) * 65;
    const float4* Kh = (const float4*)(Ks + h * 64 * KV_PITCH);
    const float4* Vh = (const float4*)(Vs + h * 64 * KV_PITCH);

    float mx = -1e30f;
    for (int m = 0; m < 64; m++) {
        float s = gb[m];
#pragma unroll
        for (int t = 0; t < 4; t++) {
            float4 kv = Kh[m * (KV_PITCH / 4) + t];
            s = fmaf(qv[4 * t + 0], kv.x, s);
            s = fmaf(qv[4 * t + 1], kv.y, s);
            s = fmaf(qv[4 * t + 2], kv.z, s);
            s = fmaf(qv[4 * t + 3], kv.w, s);
        }
        srow[m] = s;
        mx = fmaxf(mx, s);
    }
    float sum = 0.f;
    for (int m = 0; m < 64; m++) {
        float p = __expf(srow[m] - mx);
        srow[m] = p;
        sum += p;
    }
    float inv = 1.f / sum;

    float o[HD];
#pragma unroll
    for (int d = 0; d < HD; d++) o[d] = 0.f;
    for (int m = 0; m < 64; m++) {
        float p = srow[m];
#pragma unroll
        for (int t = 0; t < 4; t++) {
            float4 vv = Vh[m * (KV_PITCH / 4) + t];
            o[4 * t + 0] = fmaf(p, vv.x, o[4 * t + 0]);
            o[4 * t + 1] = fmaf(p, vv.y, o[4 * t + 1]);
            o[4 * t + 2] = fmaf(p, vv.z, o[4 * t + 2]);
            o[4 * t + 3] = fmaf(p, vv.w, o[4 * t + 3]);
        }
    }
    float* Og = g_attn + (b * C + h * HD) * HW + pix;
#pragma unroll
    for (int d = 0; d < HD; d++) Og[d * HW] = o[d] * inv;
}

// ---------------------------------------------------------------------------
// Kernel 4/5: conv3x3 via tf32 mma.sync (implicit GEMM, tap decomposition)
// block: 96 oc x 128 px (2 rows x 64 cols). 8 warps, warp tile 48x32.
// Input tile: Xs[icc(12)][row(4)][col(66)][8 ic-perm, xor-swizzled] (tf32)
// Weights: per-tap cp.async staging from pre-permuted global, double-buffered.
// ---------------------------------------------------------------------------
constexpr int XS_U32 = 12 * 4 * 66 * 8;        // 25344
constexpr int WTAP_U32 = 12 * 96 * 8;          // 9216
constexpr int CONV_MMA_SMEM = (XS_U32 + 2 * WTAP_U32) * 4;  // 175104 B

__device__ __forceinline__ void cp_async16(unsigned* smem_dst, const unsigned* gsrc) {
    unsigned sa = (unsigned)__cvta_generic_to_shared(smem_dst);
    asm volatile("cp.async.cg.shared.global [%0], [%1], 16;" :: "r"(sa), "l"(gsrc));
}

template <int PASS>
__global__ __launch_bounds__(256, 1)
void k_conv3mma(const unsigned* __restrict__ Wt, const float* __restrict__ bg) {
    const float* in = (PASS == 0) ? g_V : g_c1;
    float* out = (PASS == 0) ? g_c1 : g_c2;

    extern __shared__ unsigned smu[];
    unsigned* Xs = smu;                 // 25344
    unsigned* Wb = smu + XS_U32;        // 2 x 9216

    const int tid = threadIdx.x;
    const int lane = tid & 31;
    const int w = tid >> 5;
    const int xb = blockIdx.x * 64;
    const int yb = blockIdx.y * 2;
    const int b = blockIdx.z;

    // ---- input tile load (tf32-convert + permute + swizzle) ----
    uint2* Xs2 = (uint2*)Xs;
    for (int combo = w; combo < 192; combo += 8) {
        int icc = combo >> 4;
        int row = (combo >> 2) & 3;
        int j = combo & 3;
        int ic0 = icc * 8 + j;
        int gy = refl(yb - 1 + row);
        const float* p0 = in + ((size_t)(b * C + ic0)) * HW + gy * W;
        const float* p1 = p0 + 4 * HW;
        int cellbase = (icc * 4 + row) * 66;
        for (int col = lane; col < 66; col += 32) {
            int gx = refl(xb - 1 + col);
            unsigned v0 = f2tf32(p0[gx]);
            unsigned v1 = f2tf32(p1[gx]);
            int slot = j ^ ((col >> 2) & 3);
            Xs2[(cellbase + col) * 4 + slot] = make_uint2(v0, v1);
        }
    }

    // ---- prefetch tap 0 weights ----
    for (int i = tid; i < WTAP_U32 / 4; i += 256)
        cp_async16(Wb + i * 4, Wt + i * 4);
    asm volatile("cp.async.commit_group;");

    const int warpM = w >> 2;   // 0..1 (48 rows each)
    const int warpN = w & 3;    // 0..3 (32 px each)
    const int g = lane >> 2;    // 0..7
    const int j4 = lane & 3;    // 0..3

    float acc[3][4][4];
#pragma unroll
    for (int im = 0; im < 3; im++)
#pragma unroll
        for (int jn = 0; jn < 4; jn++)
#pragma unroll
            for (int q = 0; q < 4; q++) acc[im][jn][q] = 0.f;

    // A fragment uint2-offsets (per m-tile), kc stride = 384 uint2
    int aoff[3];
#pragma unroll
    for (int im = 0; im < 3; im++)
        aoff[im] = (warpM * 48 + im * 16 + g) * 4 + j4;

    for (int tap = 0; tap < 9; tap++) {
        const int cur = tap & 1;
        if (tap < 8) {
            const unsigned* src = Wt + (tap + 1) * WTAP_U32;
            unsigned* dst = Wb + (cur ^ 1) * WTAP_U32;
            for (int i = tid; i < WTAP_U32 / 4; i += 256)
                cp_async16(dst + i * 4, src + i * 4);
            asm volatile("cp.async.commit_group;");
            asm volatile("cp.async.wait_group 1;");
        } else {
            asm volatile("cp.async.wait_group 0;");
        }
        __syncthreads();

        const int dy = tap / 3, dx = tap % 3;

        // B fragment uint2-offsets per n-tile (kc stride = 1056 uint2)
        int xoff[4];
#pragma unroll
        for (int jn = 0; jn < 4; jn++) {
            int n0 = warpN * 32 + jn * 8;
            int r = n0 >> 6;
            int ct = (n0 & 63) + g + dx;          // tile col
            xoff[jn] = ((r + dy) * 66 + ct) * 4 + (j4 ^ ((ct >> 2) & 3));
        }
        const uint2* Wc2 = (const uint2*)(Wb + cur * WTAP_U32);

#pragma unroll 4
        for (int kc = 0; kc < 12; kc++) {
            uint2 bb[4];
#pragma unroll
            for (int jn = 0; jn < 4; jn++)
                bb[jn] = Xs2[xoff[jn] + kc * 1056];
#pragma unroll
            for (int im = 0; im < 3; im++) {
                uint2 alo = Wc2[aoff[im] + kc * 384];        // rows g   : (a0,a2)
                uint2 ahi = Wc2[aoff[im] + 32 + kc * 384];   // rows g+8 : (a1,a3)
#pragma unroll
                for (int jn = 0; jn < 4; jn++) {
                    MMA_TF32(acc[im][jn][0], acc[im][jn][1], acc[im][jn][2], acc[im][jn][3],
                             alo.x, ahi.x, alo.y, ahi.y, bb[jn].x, bb[jn].y);
                }
            }
        }
        __syncthreads();   // protect Wb[cur] before next tap's prefetch reuses it
    }

    // ---- epilogue: bias (+relu), float2 stores ----
#pragma unroll
    for (int im = 0; im < 3; im++) {
        int oc = warpM * 48 + im * 16 + g;
        float b0 = bg[oc], b1 = bg[oc + 8];
#pragma unroll
        for (int jn = 0; jn < 4; jn++) {
            int n0 = warpN * 32 + jn * 8;
            int r = n0 >> 6;
            int c = (n0 & 63) + 2 * j4;
            size_t px = (size_t)(yb + r) * W + xb + c;
            float r0 = acc[im][jn][0] + b0;
            float r1 = acc[im][jn][1] + b0;
            float r2 = acc[im][jn][2] + b1;
            float r3 = acc[im][jn][3] + b1;
            if (PASS == 0) {
                r0 = fmaxf(r0, 0.f); r1 = fmaxf(r1, 0.f);
                r2 = fmaxf(r2, 0.f); r3 = fmaxf(r3, 0.f);
            }
            *(float2*)&out[((size_t)(b * C + oc)) * HW + px] = make_float2(r0, r1);
            *(float2*)&out[((size_t)(b * C + oc + 8)) * HW + px] = make_float2(r2, r3);
        }
    }
}

// ---------------------------------------------------------------------------
// Kernel 6: proj conv1x1 on (g_c2 + g_attn) -> d_out
// ---------------------------------------------------------------------------
constexpr int PROJ_SMEM = (C * 128 + C * C + C) * 4;

__global__ __launch_bounds__(256, 1)
void k_proj(const float* __restrict__ Pw, const float* __restrict__ Pb,
            float* __restrict__ out) {
    extern __shared__ float sm[];
    float* Xs = sm;
    float* Ws = Xs + C * 128;
    float* bs = Ws + C * C;

    const int tid = threadIdx.x;
    const int pix0 = blockIdx.x * 128;
    const int b = pix0 / HW;
    const int p0 = pix0 % HW;
    const int base = b * C * HW + p0;

    for (int i = tid; i < C * 128; i += 256) {
        int idx = base + (i >> 7) * HW + (i & 127);
        Xs[i] = g_c2[idx] + g_attn[idx];
    }
    for (int i = tid; i < C * C; i += 256) Ws[i] = Pw[i];
    if (tid < C) bs[tid] = Pb[tid];
    __syncthreads();

    const int q = tid & 31;
    const int g = tid >> 5;
    const float4* Xs4 = (const float4*)Xs;

    for (int oc0 = g * 12; oc0 < g * 12 + 12; oc0 += 6) {
        float4 acc[6];
#pragma unroll
        for (int o = 0; o < 6; o++) acc[o] = make_float4(0.f, 0.f, 0.f, 0.f);
        for (int ic = 0; ic < C; ic++) {
            float4 xv = Xs4[ic * 32 + q];
#pragma unroll
            for (int o = 0; o < 6; o++) {
                float w = Ws[(oc0 + o) * C + ic];
                acc[o].x = fmaf(w, xv.x, acc[o].x);
                acc[o].y = fmaf(w, xv.y, acc[o].y);
                acc[o].z = fmaf(w, xv.z, acc[o].z);
                acc[o].w = fmaf(w, xv.w, acc[o].w);
            }
        }
#pragma unroll
        for (int o = 0; o < 6; o++) {
            int oc = oc0 + o;
            float bv = bs[oc];
            float4 r = acc[o];
            r.x += bv; r.y += bv; r.z += bv; r.w += bv;
            *(float4*)&out[(b * C + oc) * HW + p0 + q * 4] = r;
        }
    }
}

// ---------------------------------------------------------------------------
// launch
// ---------------------------------------------------------------------------
extern "C" void kernel_launch(void* const* d_in, const int* in_sizes, int n_in,
                              void* d_out, int out_size) {
    const float* X   = (const float*)d_in[0];
    const float* Vw  = (const float*)d_in[1];
    const float* Vb  = (const float*)d_in[2];
    const float* QKw = (const float*)d_in[3];
    const float* QKb = (const float*)d_in[4];
    const float* mw1 = (const float*)d_in[5];
    const float* mb1 = (const float*)d_in[6];
    const float* mw2 = (const float*)d_in[7];
    const float* mb2 = (const float*)d_in[8];
    const float* c1w = (const float*)d_in[9];
    const float* c1b = (const float*)d_in[10];
    const float* c2w = (const float*)d_in[11];
    const float* c2b = (const float*)d_in[12];
    const float* pw  = (const float*)d_in[13];
    const float* pb  = (const float*)d_in[14];
    float* out = (float*)d_out;

    cudaFuncSetAttribute(k_qkv, cudaFuncAttributeMaxDynamicSharedMemorySize, QKV_SMEM);
    cudaFuncSetAttribute(k_attn, cudaFuncAttributeMaxDynamicSharedMemorySize, ATTN_SMEM);
    cudaFuncSetAttribute(k_conv3mma<0>, cudaFuncAttributeMaxDynamicSharedMemorySize, CONV_MMA_SMEM);
    cudaFuncSetAttribute(k_conv3mma<1>, cudaFuncAttributeMaxDynamicSharedMemorySize, CONV_MMA_SMEM);
    cudaFuncSetAttribute(k_proj, cudaFuncAttributeMaxDynamicSharedMemorySize, PROJ_SMEM);

    unsigned* Wt1;
    unsigned* Wt2;
    cudaGetSymbolAddress((void**)&Wt1, g_Wt1);
    cudaGetSymbolAddress((void**)&Wt2, g_Wt2);

    k_wprep<<<(9 * 12 * 96 * 8 + 255) / 256, 256>>>(c1w, c2w);
    k_bias<<<16, 256>>>(mw1, mb1, mw2, mb2);
    k_qkv<<<NPIX / 128, 256, QKV_SMEM>>>(X, Vw, Vb, QKw, QKb);
    k_attn<<<NWIN, 384, ATTN_SMEM>>>();
    dim3 cgrid(W / 64, H / 2, B);
    k_conv3mma<0><<<cgrid, 256, CONV_MMA_SMEM>>>(Wt1, c1b);
    k_conv3mma<1><<<cgrid, 256, CONV_MMA_SMEM>>>(Wt2, c2b);
    k_proj<<<NPIX / 128, 256, PROJ_SMEM>>>(pw, pb, out);
}

// round 5
// speedup vs baseline: 1.7881x; 1.0651x over previous
#include <cuda_runtime.h>
#include <math.h>
#include <stdint.h>

// ---------------------------------------------------------------------------
// DehazeFormer block — round 5:
//   conv3x3: tf32 mma (unchanged)   |  qkv/proj: tf32 mma (V/proj hi-lo split)
//   attn: register-resident scores  |  bias: transposed for coalesced reads
// B=4, C=96, H=W=256, ws=8, nh=6, hd=16
// ---------------------------------------------------------------------------

namespace cfg {
constexpr int B = 4, C = 96, H = 256, W = 256, HW = H * W;
constexpr int NH = 6, HD = 16;
constexpr int NPIX = B * HW;
constexpr int NWIN = B * (H / 8) * (W / 8);
}
using namespace cfg;

// ---- scratch ---------------------------------------------------------------
__device__ float g_V[B * C * HW];
__device__ float g_QK[B * 2 * C * HW];
__device__ float g_attn[B * C * HW];
__device__ float g_c1[B * C * HW];
__device__ float g_c2[B * C * HW];
__device__ float g_bias[NH * 64 * 64];   // TRANSPOSED layout: [h][m][n]
// permuted tf32 conv weights: [tap][kc(12)][m(96)][8 perm]
__device__ unsigned g_Wt1[9 * 12 * 96 * 8];
__device__ unsigned g_Wt2[9 * 12 * 96 * 8];
// permuted tf32 1x1 weights: [kc(12)][m(96)][8 perm] per set
__device__ unsigned g_Wqk[2 * 12 * 96 * 8];          // oc groups 0..95, 96..191 (hi only)
__device__ unsigned g_Wv[2 * 12 * 96 * 8];           // [hi | lo]
__device__ unsigned g_Wp[2 * 12 * 96 * 8];           // [hi | lo]

__device__ __forceinline__ unsigned f2tf32(float f) {
    unsigned u;
    asm("cvt.rna.tf32.f32 %0, %1;" : "=r"(u) : "f"(f));
    return u;
}
__device__ __forceinline__ int refl(int v) {
    return v < 0 ? -v : (v > 255 ? 510 - v : v);
}

#define MMA_TF32(d0, d1, d2, d3, a0, a1, a2, a3, b0, b1)                        \
    asm volatile(                                                               \
        "mma.sync.aligned.m16n8k8.row.col.f32.tf32.tf32.f32 "                   \
        "{%0,%1,%2,%3}, {%4,%5,%6,%7}, {%8,%9}, {%0,%1,%2,%3};\n"               \
        : "+f"(d0), "+f"(d1), "+f"(d2), "+f"(d3)                                \
        : "r"(a0), "r"(a1), "r"(a2), "r"(a3), "r"(b0), "r"(b1))

// ---------------------------------------------------------------------------
// Kernel 0a: conv weight pre-permute (fp32 -> tf32)
// dst[((tap*12+kc)*96+m)*8 + pos], pos=2*(k%4)+(k/4), ic=kc*8+k
// ---------------------------------------------------------------------------
__global__ void k_wprep(const float* __restrict__ w1, const float* __restrict__ w2) {
    int e = blockIdx.x * blockDim.x + threadIdx.x;
    if (e >= 9 * 12 * 96 * 8) return;
    int pos = e & 7;
    int m = (e >> 3) % 96;
    int kc = (e >> 3) / 96 % 12;
    int tap = (e >> 3) / (96 * 12);
    int k = ((pos & 1) << 2) + (pos >> 1);
    int ic = kc * 8 + k;
    int src = m * 864 + ic * 9 + tap;
    g_Wt1[e] = f2tf32(w1[src]);
    g_Wt2[e] = f2tf32(w2[src]);
}

// ---------------------------------------------------------------------------
// Kernel 0b: 1x1 weight pre-permute. sec 0/1: QK hi; sec 2: V hi+lo; sec 3: P hi+lo
// ---------------------------------------------------------------------------
__global__ void k_wprep1x1(const float* __restrict__ QKw, const float* __restrict__ Vw,
                           const float* __restrict__ Pw) {
    int idx = blockIdx.x * blockDim.x + threadIdx.x;
    if (idx >= 4 * 9216) return;
    int sec = idx / 9216, e = idx % 9216;
    int pos = e & 7;
    int m = (e >> 3) % 96;
    int kc = (e >> 3) / 96;
    int k = ((pos & 1) << 2) + (pos >> 1);
    int ic = kc * 8 + k;
    if (sec < 2) {
        g_Wqk[sec * 9216 + e] = f2tf32(QKw[(sec * 96 + m) * 96 + ic]);
    } else {
        float v = (sec == 2) ? Vw[m * 96 + ic] : Pw[m * 96 + ic];
        unsigned h = f2tf32(v);
        unsigned l = f2tf32(v - __uint_as_float(h));
        if (sec == 2) { g_Wv[e] = h; g_Wv[9216 + e] = l; }
        else          { g_Wp[e] = h; g_Wp[9216 + e] = l; }
    }
}

// ---------------------------------------------------------------------------
// Kernel 1: relative-position bias MLP -> g_bias[h][m][n]  (transposed store)
// ---------------------------------------------------------------------------
__global__ void k_bias(const float* __restrict__ w1, const float* __restrict__ b1,
                       const float* __restrict__ w2, const float* __restrict__ b2) {
    int idx = blockIdx.x * blockDim.x + threadIdx.x;
    if (idx >= 64 * 64) return;
    int n = idx >> 6, m = idx & 63;
    float dy = (float)((n >> 3) - (m >> 3));
    float dx = (float)((n & 7) - (m & 7));
    float sy = (dy > 0.f) ? 1.f : ((dy < 0.f) ? -1.f : 0.f);
    float sx = (dx > 0.f) ? 1.f : ((dx < 0.f) ? -1.f : 0.f);
    float r0 = sy * log1pf(fabsf(dy));
    float r1 = sx * log1pf(fabsf(dx));
    float acc[NH];
#pragma unroll
    for (int h = 0; h < NH; h++) acc[h] = b2[h];
    for (int k = 0; k < 256; k++) {
        float hk = fmaf(r0, w1[k], fmaf(r1, w1[256 + k], b1[k]));
        hk = fmaxf(hk, 0.f);
#pragma unroll
        for (int h = 0; h < NH; h++) acc[h] = fmaf(hk, w2[k * NH + h], acc[h]);
    }
#pragma unroll
    for (int h = 0; h < NH; h++) g_bias[(h * 64 + m) * 64 + n] = acc[h];  // [h][m][n]
}

// ---------------------------------------------------------------------------
// Kernel 2: conv1x1 GEMM via tf32 mma.
// MODE 0: QK (plain tf32, grid.y = oc group), 1: V (hi/lo split), 2: proj (split, in=c2+attn)
// Block: 96 oc x 128 px, 8 warps, warp tile 48x32, K=96 (kc=12).
// ---------------------------------------------------------------------------
constexpr int G_XU2 = 12 * 128 * 4;   // uint2 per X set (6144)
constexpr int G_WU32 = 12 * 96 * 8;   // u32 per W set (9216)
constexpr int C1X1_SMEM_PLAIN = (2 * G_XU2 + G_WU32) * 4;        // 86016
constexpr int C1X1_SMEM_SPLIT = (4 * G_XU2 + 2 * G_WU32) * 4;    // 172032

template <int MODE>
__global__ __launch_bounds__(256, 1)
void k_c1x1(const float* __restrict__ src,
            const unsigned* __restrict__ Whi, const unsigned* __restrict__ Wlo,
            const float* __restrict__ bias, float* __restrict__ dstp) {
    constexpr bool SPLIT = (MODE != 0);
    extern __shared__ unsigned smu[];
    uint2* Xh = (uint2*)smu;
    uint2* Xl = (uint2*)(smu + 2 * G_XU2);
    unsigned* Wh = smu + (SPLIT ? 4 * G_XU2 : 2 * G_XU2);
    unsigned* Wl = Wh + G_WU32;

    const int tid = threadIdx.x, lane = tid & 31, w = tid >> 5;
    const int pix0 = blockIdx.x * 128;
    const int b = pix0 / HW, p0 = pix0 % HW;
    const int ocg = (MODE == 0) ? blockIdx.y : 0;

    // ---- X tile: hi/lo tf32 convert + slot permute + xor swizzle ----
    for (int combo = w; combo < 48; combo += 8) {
        int kc = combo >> 2, j = combo & 3;
        size_t base0 = ((size_t)(b * C + kc * 8 + j)) * HW + p0;
        for (int col = lane; col < 128; col += 32) {
            float x0, x1;
            if (MODE == 2) {
                x0 = g_c2[base0 + col] + g_attn[base0 + col];
                x1 = g_c2[base0 + 4 * HW + col] + g_attn[base0 + 4 * HW + col];
            } else {
                x0 = src[base0 + col];
                x1 = src[base0 + 4 * HW + col];
            }
            unsigned h0 = f2tf32(x0), h1 = f2tf32(x1);
            int slot = j ^ ((col >> 2) & 3);
            Xh[(kc * 128 + col) * 4 + slot] = make_uint2(h0, h1);
            if (SPLIT) {
                unsigned l0 = f2tf32(x0 - __uint_as_float(h0));
                unsigned l1 = f2tf32(x1 - __uint_as_float(h1));
                Xl[(kc * 128 + col) * 4 + slot] = make_uint2(l0, l1);
            }
        }
    }
    for (int i = tid; i < G_WU32; i += 256) {
        Wh[i] = Whi[ocg * G_WU32 + i];
        if (SPLIT) Wl[i] = Wlo[i];
    }
    __syncthreads();

    const int warpM = w >> 2, warpN = w & 3;
    const int g = lane >> 2, j4 = lane & 3;

    float acc[3][4][4];
#pragma unroll
    for (int im = 0; im < 3; im++)
#pragma unroll
        for (int jn = 0; jn < 4; jn++)
#pragma unroll
            for (int q = 0; q < 4; q++) acc[im][jn][q] = 0.f;

    int aoff[3];
#pragma unroll
    for (int im = 0; im < 3; im++)
        aoff[im] = (warpM * 48 + im * 16 + g) * 4 + j4;     // uint2; kc stride 384
    int xoff[4];
#pragma unroll
    for (int jn = 0; jn < 4; jn++) {
        int col = warpN * 32 + jn * 8 + g;
        xoff[jn] = col * 4 + (j4 ^ ((col >> 2) & 3));        // uint2; kc stride 512
    }
    const uint2* Wh2 = (const uint2*)Wh;
    const uint2* Wl2 = (const uint2*)Wl;

#pragma unroll 4
    for (int kc = 0; kc < 12; kc++) {
        uint2 bh[4], bl[4];
#pragma unroll
        for (int jn = 0; jn < 4; jn++) bh[jn] = Xh[xoff[jn] + kc * 512];
        if (SPLIT) {
#pragma unroll
            for (int jn = 0; jn < 4; jn++) bl[jn] = Xl[xoff[jn] + kc * 512];
        }
#pragma unroll
        for (int im = 0; im < 3; im++) {
            uint2 alo = Wh2[aoff[im] + kc * 384];
            uint2 ahi = Wh2[aoff[im] + 32 + kc * 384];
#pragma unroll
            for (int jn = 0; jn < 4; jn++)
                MMA_TF32(acc[im][jn][0], acc[im][jn][1], acc[im][jn][2], acc[im][jn][3],
                         alo.x, ahi.x, alo.y, ahi.y, bh[jn].x, bh[jn].y);
            if (SPLIT) {
#pragma unroll
                for (int jn = 0; jn < 4; jn++)
                    MMA_TF32(acc[im][jn][0], acc[im][jn][1], acc[im][jn][2], acc[im][jn][3],
                             alo.x, ahi.x, alo.y, ahi.y, bl[jn].x, bl[jn].y);
                uint2 clo = Wl2[aoff[im] + kc * 384];
                uint2 chi = Wl2[aoff[im] + 32 + kc * 384];
#pragma unroll
                for (int jn = 0; jn < 4; jn++)
                    MMA_TF32(acc[im][jn][0], acc[im][jn][1], acc[im][jn][2], acc[im][jn][3],
                             clo.x, chi.x, clo.y, chi.y, bh[jn].x, bh[jn].y);
            }
        }
    }

    // ---- epilogue ----
#pragma unroll
    for (int im = 0; im < 3; im++) {
        int ocl = warpM * 48 + im * 16 + g;
        float b0 = bias[ocg * 96 + ocl];
        float b1 = bias[ocg * 96 + ocl + 8];
        size_t ch = (MODE == 0) ? (size_t)(b * 192 + ocg * 96 + ocl) : (size_t)(b * 96 + ocl);
        float* outp = (MODE == 0) ? g_QK : (MODE == 1) ? g_V : dstp;
#pragma unroll
        for (int jn = 0; jn < 4; jn++) {
            int ncol = warpN * 32 + jn * 8 + 2 * j4;
            size_t px = ch * HW + p0 + ncol;
            *(float2*)&outp[px] = make_float2(acc[im][jn][0] + b0, acc[im][jn][1] + b0);
            *(float2*)&outp[px + 8 * HW] = make_float2(acc[im][jn][2] + b1, acc[im][jn][3] + b1);
        }
    }
}

// ---------------------------------------------------------------------------
// Kernel 3: window attention — register-resident scores, smem only for K/V.
// 384 thr = 6 heads x 64 rows. K/V pitch 16 floats (broadcast reads).
// ---------------------------------------------------------------------------
constexpr int ATTN_SMEM = 2 * NH * 64 * 16 * 4;   // 49152 B

__global__ __launch_bounds__(384, 1)
void k_attn() {
    extern __shared__ float sm[];
    float* Ks = sm;                  // [h][n][16]
    float* Vs = sm + NH * 64 * 16;

    const int tid = threadIdx.x;
    const int win = blockIdx.x;
    const int b = win >> 10;
    const int wy = (win >> 5) & 31, wx = win & 31;
    const int h = tid / 64, n = tid & 63;
    const int pix = (wy * 8 + (n >> 3)) * W + wx * 8 + (n & 7);

    const float* Qg = g_QK + (b * 192 + h * HD) * HW + pix;
    const float* Kg = g_QK + (b * 192 + 96 + h * HD) * HW + pix;
    const float* Vg = g_V + (b * C + h * HD) * HW + pix;

    float qv[HD];
#pragma unroll
    for (int d = 0; d < HD; d++) {
        qv[d] = Qg[d * HW] * 0.25f;   // scale = hd^-0.5
        Ks[(h * 64 + n) * 16 + d] = Kg[d * HW];
        Vs[(h * 64 + n) * 16 + d] = Vg[d * HW];
    }
    __syncthreads();

    const float* gb = g_bias + h * 64 * 64 + n;     // [h][m][n]: read gb[m*64]
    const float4* Kh = (const float4*)(Ks + h * 64 * 16);
    const float4* Vh = (const float4*)(Vs + h * 64 * 16);

    float s[64];
    float mx = -1e30f;
#pragma unroll
    for (int m = 0; m < 64; m++) {
        float v = gb[m * 64];
#pragma unroll
        for (int t = 0; t < 4; t++) {
            float4 kv = Kh[m * 4 + t];
            v = fmaf(qv[4 * t + 0], kv.x, v);
            v = fmaf(qv[4 * t + 1], kv.y, v);
            v = fmaf(qv[4 * t + 2], kv.z, v);
            v = fmaf(qv[4 * t + 3], kv.w, v);
        }
        s[m] = v;
        mx = fmaxf(mx, v);
    }
    float sum = 0.f;
#pragma unroll
    for (int m = 0; m < 64; m++) {
        s[m] = __expf(s[m] - mx);
        sum += s[m];
    }
    float inv = 1.f / sum;

    float o[HD];
#pragma unroll
    for (int d = 0; d < HD; d++) o[d] = 0.f;
#pragma unroll
    for (int m = 0; m < 64; m++) {
        float p = s[m];
#pragma unroll
        for (int t = 0; t < 4; t++) {
            float4 vv = Vh[m * 4 + t];
            o[4 * t + 0] = fmaf(p, vv.x, o[4 * t + 0]);
            o[4 * t + 1] = fmaf(p, vv.y, o[4 * t + 1]);
            o[4 * t + 2] = fmaf(p, vv.z, o[4 * t + 2]);
            o[4 * t + 3] = fmaf(p, vv.w, o[4 * t + 3]);
        }
    }
    float* Og = g_attn + (b * C + h * HD) * HW + pix;
#pragma unroll
    for (int d = 0; d < HD; d++) Og[d * HW] = o[d] * inv;
}

// ---------------------------------------------------------------------------
// Kernel 4/5: conv3x3 via tf32 mma (unchanged from round 3)
// ---------------------------------------------------------------------------
constexpr int XS_U32 = 12 * 4 * 66 * 8;        // 25344
constexpr int WTAP_U32 = 12 * 96 * 8;          // 9216
constexpr int CONV_MMA_SMEM = (XS_U32 + 2 * WTAP_U32) * 4;  // 175104 B

__device__ __forceinline__ void cp_async16(unsigned* smem_dst, const unsigned* gsrc) {
    unsigned sa = (unsigned)__cvta_generic_to_shared(smem_dst);
    asm volatile("cp.async.cg.shared.global [%0], [%1], 16;" :: "r"(sa), "l"(gsrc));
}

template <int PASS>
__global__ __launch_bounds__(256, 1)
void k_conv3mma(const unsigned* __restrict__ Wt, const float* __restrict__ bg) {
    const float* in = (PASS == 0) ? g_V : g_c1;
    float* out = (PASS == 0) ? g_c1 : g_c2;

    extern __shared__ unsigned smu[];
    unsigned* Xs = smu;
    unsigned* Wb = smu + XS_U32;

    const int tid = threadIdx.x;
    const int lane = tid & 31;
    const int w = tid >> 5;
    const int xb = blockIdx.x * 64;
    const int yb = blockIdx.y * 2;
    const int b = blockIdx.z;

    uint2* Xs2 = (uint2*)Xs;
    for (int combo = w; combo < 192; combo += 8) {
        int icc = combo >> 4;
        int row = (combo >> 2) & 3;
        int j = combo & 3;
        int ic0 = icc * 8 + j;
        int gy = refl(yb - 1 + row);
        const float* p0 = in + ((size_t)(b * C + ic0)) * HW + gy * W;
        const float* p1 = p0 + 4 * HW;
        int cellbase = (icc * 4 + row) * 66;
        for (int col = lane; col < 66; col += 32) {
            int gx = refl(xb - 1 + col);
            unsigned v0 = f2tf32(p0[gx]);
            unsigned v1 = f2tf32(p1[gx]);
            int slot = j ^ ((col >> 2) & 3);
            Xs2[(cellbase + col) * 4 + slot] = make_uint2(v0, v1);
        }
    }

    for (int i = tid; i < WTAP_U32 / 4; i += 256)
        cp_async16(Wb + i * 4, Wt + i * 4);
    asm volatile("cp.async.commit_group;");

    const int warpM = w >> 2;
    const int warpN = w & 3;
    const int g = lane >> 2;
    const int j4 = lane & 3;

    float acc[3][4][4];
#pragma unroll
    for (int im = 0; im < 3; im++)
#pragma unroll
        for (int jn = 0; jn < 4; jn++)
#pragma unroll
            for (int q = 0; q < 4; q++) acc[im][jn][q] = 0.f;

    int aoff[3];
#pragma unroll
    for (int im = 0; im < 3; im++)
        aoff[im] = (warpM * 48 + im * 16 + g) * 4 + j4;

    for (int tap = 0; tap < 9; tap++) {
        const int cur = tap & 1;
        if (tap < 8) {
            const unsigned* src = Wt + (tap + 1) * WTAP_U32;
            unsigned* dst = Wb + (cur ^ 1) * WTAP_U32;
            for (int i = tid; i < WTAP_U32 / 4; i += 256)
                cp_async16(dst + i * 4, src + i * 4);
            asm volatile("cp.async.commit_group;");
            asm volatile("cp.async.wait_group 1;");
        } else {
            asm volatile("cp.async.wait_group 0;");
        }
        __syncthreads();

        const int dy = tap / 3, dx = tap % 3;

        int xoff[4];
#pragma unroll
        for (int jn = 0; jn < 4; jn++) {
            int n0 = warpN * 32 + jn * 8;
            int r = n0 >> 6;
            int ct = (n0 & 63) + g + dx;
            xoff[jn] = ((r + dy) * 66 + ct) * 4 + (j4 ^ ((ct >> 2) & 3));
        }
        const uint2* Wc2 = (const uint2*)(Wb + cur * WTAP_U32);

#pragma unroll 4
        for (int kc = 0; kc < 12; kc++) {
            uint2 bb[4];
#pragma unroll
            for (int jn = 0; jn < 4; jn++)
                bb[jn] = Xs2[xoff[jn] + kc * 1056];
#pragma unroll
            for (int im = 0; im < 3; im++) {
                uint2 alo = Wc2[aoff[im] + kc * 384];
                uint2 ahi = Wc2[aoff[im] + 32 + kc * 384];
#pragma unroll
                for (int jn = 0; jn < 4; jn++) {
                    MMA_TF32(acc[im][jn][0], acc[im][jn][1], acc[im][jn][2], acc[im][jn][3],
                             alo.x, ahi.x, alo.y, ahi.y, bb[jn].x, bb[jn].y);
                }
            }
        }
        __syncthreads();
    }

#pragma unroll
    for (int im = 0; im < 3; im++) {
        int oc = warpM * 48 + im * 16 + g;
        float b0 = bg[oc], b1 = bg[oc + 8];
#pragma unroll
        for (int jn = 0; jn < 4; jn++) {
            int n0 = warpN * 32 + jn * 8;
            int r = n0 >> 6;
            int c = (n0 & 63) + 2 * j4;
            size_t px = (size_t)(yb + r) * W + xb + c;
            float r0 = acc[im][jn][0] + b0;
            float r1 = acc[im][jn][1] + b0;
            float r2 = acc[im][jn][2] + b1;
            float r3 = acc[im][jn][3] + b1;
            if (PASS == 0) {
                r0 = fmaxf(r0, 0.f); r1 = fmaxf(r1, 0.f);
                r2 = fmaxf(r2, 0.f); r3 = fmaxf(r3, 0.f);
            }
            *(float2*)&out[((size_t)(b * C + oc)) * HW + px] = make_float2(r0, r1);
            *(float2*)&out[((size_t)(b * C + oc + 8)) * HW + px] = make_float2(r2, r3);
        }
    }
}

// ---------------------------------------------------------------------------
// launch
// ---------------------------------------------------------------------------
extern "C" void kernel_launch(void* const* d_in, const int* in_sizes, int n_in,
                              void* d_out, int out_size) {
    const float* X   = (const float*)d_in[0];
    const float* Vw  = (const float*)d_in[1];
    const float* Vb  = (const float*)d_in[2];
    const float* QKw = (const float*)d_in[3];
    const float* QKb = (const float*)d_in[4];
    const float* mw1 = (const float*)d_in[5];
    const float* mb1 = (const float*)d_in[6];
    const float* mw2 = (const float*)d_in[7];
    const float* mb2 = (const float*)d_in[8];
    const float* c1w = (const float*)d_in[9];
    const float* c1b = (const float*)d_in[10];
    const float* c2w = (const float*)d_in[11];
    const float* c2b = (const float*)d_in[12];
    const float* pw  = (const float*)d_in[13];
    const float* pb  = (const float*)d_in[14];
    float* out = (float*)d_out;

    cudaFuncSetAttribute(k_attn, cudaFuncAttributeMaxDynamicSharedMemorySize, ATTN_SMEM);
    cudaFuncSetAttribute(k_conv3mma<0>, cudaFuncAttributeMaxDynamicSharedMemorySize, CONV_MMA_SMEM);
    cudaFuncSetAttribute(k_conv3mma<1>, cudaFuncAttributeMaxDynamicSharedMemorySize, CONV_MMA_SMEM);
    cudaFuncSetAttribute(k_c1x1<0>, cudaFuncAttributeMaxDynamicSharedMemorySize, C1X1_SMEM_PLAIN);
    cudaFuncSetAttribute(k_c1x1<1>, cudaFuncAttributeMaxDynamicSharedMemorySize, C1X1_SMEM_SPLIT);
    cudaFuncSetAttribute(k_c1x1<2>, cudaFuncAttributeMaxDynamicSharedMemorySize, C1X1_SMEM_SPLIT);

    unsigned *Wt1, *Wt2, *Wqk, *Wv, *Wp;
    cudaGetSymbolAddress((void**)&Wt1, g_Wt1);
    cudaGetSymbolAddress((void**)&Wt2, g_Wt2);
    cudaGetSymbolAddress((void**)&Wqk, g_Wqk);
    cudaGetSymbolAddress((void**)&Wv, g_Wv);
    cudaGetSymbolAddress((void**)&Wp, g_Wp);

    k_wprep<<<(9 * 12 * 96 * 8 + 255) / 256, 256>>>(c1w, c2w);
    k_wprep1x1<<<(4 * 9216 + 255) / 256, 256>>>(QKw, Vw, pw);
    k_bias<<<16, 256>>>(mw1, mb1, mw2, mb2);

    k_c1x1<0><<<dim3(NPIX / 128, 2), 256, C1X1_SMEM_PLAIN>>>(X, Wqk, Wqk, QKb, nullptr);
    k_c1x1<1><<<NPIX / 128, 256, C1X1_SMEM_SPLIT>>>(X, Wv, Wv + 9216, Vb, nullptr);

    k_attn<<<NWIN, 384, ATTN_SMEM>>>();

    dim3 cgrid(W / 64, H / 2, B);
    k_conv3mma<0><<<cgrid, 256, CONV_MMA_SMEM>>>(Wt1, c1b);
    k_conv3mma<1><<<cgrid, 256, CONV_MMA_SMEM>>>(Wt2, c2b);

    k_c1x1<2><<<NPIX / 128, 256, C1X1_SMEM_SPLIT>>>(nullptr, Wp, Wp + 9216, pb, out);
}